// round 14
// baseline (speedup 1.0000x reference)
#include <cuda_runtime.h>
#include <cuda_fp16.h>
#include <cstdint>

// Problem constants
#define NV_TOT 20000
#define IN_DIM 150
#define H_DIM  64
#define O_DIM  128
#define PT_DIM 80
#define CONN_STRIDE 240   // PT_DIM * 3

#define MTILE 64
#define NTILES ((NV_TOT + MTILE - 1) / MTILE)   // 313
#define NSPLIT 4
#define CHUNKS_PER_SPLIT (PT_DIM / NSPLIT)      // 20
#define PART_STRIDE ((long)NV_TOT * O_DIM)      // 2,560,000 floats

// SMEM layout (bytes from dynamic base): two buffers of A(8K)+B(16K)
#define A_O     0
#define B_O     8192
#define BUF_STRIDE 24576
#define SMEM_TOTAL (2 * BUF_STRIDE)   // 49152

// Scratch
__device__ __align__(16) __half   g_h16[NV_TOT * H_DIM];   // fp16 hidden
__device__ __align__(16) uint32_t g_bf[PT_DIM * 4096];     // B fp16, fragment layout
__device__ __align__(16) float    g_part[(long)NSPLIT * PART_STRIDE]; // 41MB partials

// ---------------------------------------------------------------------------
__device__ __forceinline__ void mma16816(float* d, const uint32_t* a, const uint32_t* b) {
    asm volatile("mma.sync.aligned.m16n8k16.row.col.f32.f16.f16.f32 "
                 "{%0,%1,%2,%3}, {%4,%5,%6,%7}, {%8,%9}, {%0,%1,%2,%3};"
                 : "+f"(d[0]), "+f"(d[1]), "+f"(d[2]), "+f"(d[3])
                 : "r"(a[0]), "r"(a[1]), "r"(a[2]), "r"(a[3]),
                   "r"(b[0]), "r"(b[1]));
}

// ---------------------------------------------------------------------------
// prep B: Wg[o][h][pt] -> fp16, MMA fragment layout:
// word = ((ntile*4 + ks)*32 + gro*4 + q)*2 + r4
// ---------------------------------------------------------------------------
__global__ void __launch_bounds__(256) k_prepB(const float* __restrict__ Wg) {
    int b = blockIdx.x;
    int pt = b >> 2;
    int base = (b & 3) * 1024 + threadIdx.x;
#pragma unroll
    for (int i = 0; i < 4; i++) {
        int item = base + i * 256;            // item = o*32 + hp
        int o = item >> 5, hp = item & 31;
        float w0 = Wg[(o * H_DIM + 2 * hp) * PT_DIM + pt];
        float w1 = Wg[(o * H_DIM + 2 * hp + 1) * PT_DIM + pt];
        __half2 hh = __floats2half2_rn(w0, w1);
        int ntile = o >> 3, gro = o & 7;
        int ks = hp >> 3, r4 = (hp >> 2) & 1, q = hp & 3;
        int word = ((ntile * 4 + ks) * 32 + gro * 4 + q) * 2 + r4;
        g_bf[pt * 4096 + word] = *(uint32_t*)&hh;
    }
}

// ---------------------------------------------------------------------------
// h = relu(x @ W1^T) -> g_h16 (fp16)
// ---------------------------------------------------------------------------
__global__ void __launch_bounds__(256) k_hidden(const float* __restrict__ x,
                                                const float* __restrict__ W1) {
    __shared__ float W1t[IN_DIM * H_DIM];
    int t = threadIdx.x;
    for (int idx = t; idx < IN_DIM * H_DIM; idx += 256) {
        int i = idx >> 6, h = idx & 63;
        W1t[idx] = W1[h * IN_DIM + i];
    }
    __syncthreads();

    int vbase = blockIdx.x * 32;
    int h = t & 63;
    int vg = t >> 6;
    const float* xrow = x + (long)(vbase + vg * 8) * IN_DIM;
    float acc[8];
#pragma unroll
    for (int j = 0; j < 8; j++) acc[j] = 0.0f;
    for (int i = 0; i < IN_DIM; i += 2) {
        float w0 = W1t[i * H_DIM + h];
        float w1 = W1t[(i + 1) * H_DIM + h];
#pragma unroll
        for (int j = 0; j < 8; j++) {
            float2 xv = *(const float2*)(xrow + j * IN_DIM + i);
            acc[j] = fmaf(xv.x, w0, acc[j]);
            acc[j] = fmaf(xv.y, w1, acc[j]);
        }
    }
#pragma unroll
    for (int j = 0; j < 8; j++)
        g_h16[(long)(vbase + vg * 8 + j) * H_DIM + h] = __float2half(fmaxf(acc[j], 0.0f));
}

// ---------------------------------------------------------------------------
// Main: split-K. 1252 blocks = 313 tiles x 4 splits; each block does 20 of the
// 80 pt-chunks for a 64-vertex tile and writes fp32 partials to its split's
// buffer. 512 threads (16 warps, warp tile 16x32), occ 2. Single-term fp16
// mma.sync; fp16 gather; conn prefetch depth 2; gather LDGs before mma(c).
// ---------------------------------------------------------------------------
__global__ void __launch_bounds__(512, 2) k_main(const int*   __restrict__ conn_idx,
                                                 const float* __restrict__ conn_w) {
    extern __shared__ char smem_c[];

    int t = threadIdx.x;
    int wid = t >> 5, l = t & 31;
    int tile = blockIdx.x >> 2;
    int split = blockIdx.x & 3;
    int vbase = tile * MTILE;
    int c0 = split * CHUNKS_PER_SPLIT;
    int c1 = c0 + CHUNKS_PER_SPLIT;
    float* pout = g_part + (long)split * PART_STRIDE;

    int mtile = wid & 3;       // m0 = mtile*16
    int nq = wid >> 2;         // n0 = nq*32
    int gr = l >> 2, q = l & 3;

    float acc[4][4];
#pragma unroll
    for (int a2 = 0; a2 < 4; a2++)
#pragma unroll
        for (int a3 = 0; a3 < 4; a3++) acc[a2][a3] = 0.0f;

    // conn loader: lanes 0..11 load idx, 12..23 load weights, for this warp's
    // 4 gather rows (wid + 16*i), chunk c. OOB rows -> 0.
    auto ldconn = [&](int c) -> uint32_t {
        uint32_t v = 0;
        if (l < 12) {
            int r = l / 3, k = l - 3 * r;
            int gv = vbase + wid + 16 * r;
            if (gv < NV_TOT)
                v = (uint32_t)conn_idx[(long)gv * CONN_STRIDE + c * 3 + k];
        } else if (l < 24) {
            int ll = l - 12;
            int r = ll / 3, k = ll - 3 * r;
            int gv = vbase + wid + 16 * r;
            if (gv < NV_TOT)
                v = __float_as_uint(conn_w[(long)gv * CONN_STRIDE + c * 3 + k]);
        }
        return v;
    };

    // issue the 12 gather LDGs (fp16 rows, one uint32 = half2 per lane)
    auto ldgather = [&](uint32_t connv, uint32_t* hv) {
#pragma unroll
        for (int i = 0; i < 4; i++) {
            int i0 = (int)__shfl_sync(0xffffffffu, connv, i * 3 + 0);
            int i1 = (int)__shfl_sync(0xffffffffu, connv, i * 3 + 1);
            int i2 = (int)__shfl_sync(0xffffffffu, connv, i * 3 + 2);
            hv[i * 3 + 0] = *((const uint32_t*)(g_h16 + (long)i0 * H_DIM) + l);
            hv[i * 3 + 1] = *((const uint32_t*)(g_h16 + (long)i1 * H_DIM) + l);
            hv[i * 3 + 2] = *((const uint32_t*)(g_h16 + (long)i2 * H_DIM) + l);
        }
    };

    // combine + convert + store A into fragment layout
    auto stsA = [&](uint32_t connv, const uint32_t* hv, char* buf) {
#pragma unroll
        for (int i = 0; i < 4; i++) {
            float w0 = __uint_as_float(__shfl_sync(0xffffffffu, connv, 12 + i * 3 + 0));
            float w1 = __uint_as_float(__shfl_sync(0xffffffffu, connv, 12 + i * 3 + 1));
            float w2 = __uint_as_float(__shfl_sync(0xffffffffu, connv, 12 + i * 3 + 2));
            float2 h0 = __half22float2(*(const __half2*)&hv[i * 3 + 0]);
            float2 h1 = __half22float2(*(const __half2*)&hv[i * 3 + 1]);
            float2 h2 = __half22float2(*(const __half2*)&hv[i * 3 + 2]);
            float ax = fmaf(w2, h2.x, fmaf(w1, h1.x, w0 * h0.x));
            float ay = fmaf(w2, h2.y, fmaf(w1, h1.y, w0 * h0.y));
            __half2 hh = __floats2half2_rn(ax, ay);
            int vv = wid + 16 * i;
            int mt2 = vv >> 4, r = vv & 15, grv = r & 7, half = r >> 3;
            int ks = l >> 3, r4 = (l >> 2) & 1, qq = l & 3;
            int slot = (grv * 4 + qq) ^ ((ks * 5) & 31);
            int word = ((mt2 * 4 + ks) * 32 + slot) * 4 + r4 * 2 + half;
            ((uint32_t*)(buf + A_O))[word] = *(uint32_t*)&hh;
        }
    };

    // B tile: verbatim coalesced copy (fragment layout), 16KB / 512 threads
    auto stageB = [&](int c, char* buf) {
        const float4* src = (const float4*)(g_bf + c * 4096);
        float4* dst = (float4*)(buf + B_O);
        dst[t]       = src[t];
        dst[t + 512] = src[t + 512];
    };

    auto mma_chunk = [&](int bsel) {
        const char* buf = smem_c + bsel * BUF_STRIDE;
#pragma unroll
        for (int ks = 0; ks < 4; ks++) {
            int aslot = l ^ ((ks * 5) & 31);
            uint4 aF = ((const uint4*)(buf + A_O))[(mtile * 4 + ks) * 32 + aslot];
            uint2 bF[4];
#pragma unroll
            for (int nt = 0; nt < 4; nt++)
                bF[nt] = ((const uint2*)(buf + B_O))[((nq * 4 + nt) * 4 + ks) * 32 + l];
#pragma unroll
            for (int nt = 0; nt < 4; nt++)
                mma16816(acc[nt], (const uint32_t*)&aF, (const uint32_t*)&bF[nt]);
        }
    };

    uint32_t hv[12];

    // prologue: chunk c0 staged directly; conn(c0+1) in flight
    uint32_t conn0 = ldconn(c0);
    uint32_t connNext = ldconn(c0 + 1);
    ldgather(conn0, hv);
    stageB(c0, smem_c);
    stsA(conn0, hv, smem_c);
    __syncthreads();

    for (int c = c0; c < c1; c++) {
        int bsel = c & 1;
        uint32_t connFut = (c + 2 < c1) ? ldconn(c + 2) : 0u;
        if (c + 1 < c1) ldgather(connNext, hv);   // LDGs in flight...
        mma_chunk(bsel);                          // ...covered by MMAs
        if (c + 1 < c1) {
            char* nbuf = smem_c + (bsel ^ 1) * BUF_STRIDE;
            stageB(c + 1, nbuf);
            stsA(connNext, hv, nbuf);
        }
        connNext = connFut;
        __syncthreads();
    }

    // write fp32 partials (no bias/norm here; deterministic fixed-order sum later)
#pragma unroll
    for (int qh = 0; qh < 2; qh++) {
        int row = mtile * 16 + gr + qh * 8;
        int row_g = vbase + row;
        if (row_g < NV_TOT) {
#pragma unroll
            for (int nt = 0; nt < 4; nt++) {
                float2 o2;
                o2.x = acc[nt][qh * 2 + 0];
                o2.y = acc[nt][qh * 2 + 1];
                *(float2*)&pout[(long)row_g * O_DIM + nq * 32 + nt * 8 + q * 2] = o2;
            }
        }
    }
}

// ---------------------------------------------------------------------------
// Final: sum 4 partials + bias, L2-normalize, store. One warp per vertex.
// ---------------------------------------------------------------------------
__global__ void __launch_bounds__(256) k_final(const float* __restrict__ bg,
                                               float* __restrict__ out) {
    int t = threadIdx.x;
    int w = t >> 5, l = t & 31;
    long v = (long)blockIdx.x * 8 + w;           // grid 2500 -> 20000 exact
    long base = v * O_DIM + l * 4;

    float4 s = *(const float4*)&g_part[base];
#pragma unroll
    for (int sp = 1; sp < NSPLIT; sp++) {
        float4 p = *(const float4*)&g_part[sp * PART_STRIDE + base];
        s.x += p.x; s.y += p.y; s.z += p.z; s.w += p.w;
    }
    float4 b = *(const float4*)&bg[l * 4];
    s.x += b.x; s.y += b.y; s.z += b.z; s.w += b.w;

    float part = s.x * s.x + s.y * s.y + s.z * s.z + s.w * s.w;
#pragma unroll
    for (int off = 16; off > 0; off >>= 1)
        part += __shfl_xor_sync(0xffffffffu, part, off);
    float inv = rsqrtf(part);

    float4 o4;
    o4.x = s.x * inv; o4.y = s.y * inv; o4.z = s.z * inv; o4.w = s.w * inv;
    *(float4*)&out[base] = o4;
}

// ---------------------------------------------------------------------------
extern "C" void kernel_launch(void* const* d_in, const int* in_sizes, int n_in,
                              void* d_out, int out_size) {
    const float* x    = (const float*)d_in[0];
    const int*   cidx = (const int*)d_in[1];
    const float* cw   = (const float*)d_in[2];
    const float* W1   = (const float*)d_in[3];
    const float* Wg   = (const float*)d_in[4];
    const float* bg   = (const float*)d_in[5];
    float* out = (float*)d_out;

    cudaFuncSetAttribute(k_main, cudaFuncAttributeMaxDynamicSharedMemorySize,
                         SMEM_TOTAL);

    k_prepB<<<PT_DIM * 4, 256>>>(Wg);
    k_hidden<<<NV_TOT / 32, 256>>>(x, W1);
    k_main<<<NTILES * NSPLIT, 512, SMEM_TOTAL>>>(cidx, cw);
    k_final<<<NV_TOT / 8, 256>>>(bg, out);
}